// round 3
// baseline (speedup 1.0000x reference)
#include <cuda_runtime.h>
#include <cuda_bf16.h>
#include <math.h>

// Problem dims
#define Bb   16
#define Ll   256
#define Dd   768
#define Hh   12
#define HDd  64
#define NLl  4
#define Ff   3072
#define Ee   50
#define Cc   2
#define ROWS (Bb * Ll)   // 4096

// ---------------------------------------------------------------------------
// Scratch (device globals; no allocations allowed)
// ---------------------------------------------------------------------------
__device__ float g_h [ROWS * Dd];
__device__ float g_q [ROWS * Dd];
__device__ float g_k [ROWS * Dd];
__device__ float g_v [ROWS * Dd];
__device__ float g_ao[ROWS * Dd];
__device__ float g_t [ROWS * Dd];
__device__ float g_ff[ROWS * Ff];
__device__ float g_qe[ROWS * Hh * Ee];

// ---------------------------------------------------------------------------
// Embedding: h[b,l,d] = word_emb[ids[b,l], d] + pos_emb(l, d)
// ---------------------------------------------------------------------------
__global__ void embed_kernel(const int* __restrict__ ids,
                             const float* __restrict__ wemb,
                             float* __restrict__ h) {
    int idx = blockIdx.x * blockDim.x + threadIdx.x;   // < ROWS*Dd
    int d   = idx % Dd;
    int row = idx / Dd;
    int l   = row % Ll;
    int j   = d >> 1;
    float ang = (float)l * expf(-9.210340371976184f * (float)(2 * j) / (float)Dd);
    float pe  = (d & 1) ? cosf(ang) : sinf(ang);
    h[idx] = wemb[(size_t)ids[row] * Dd + d] + pe;
}

// ---------------------------------------------------------------------------
// Generic fp32 GEMM: C[M,N] = A[M,K] @ B[K,N] + bias[N]  (optional ReLU)
// BM=BN=128, BK=16, 256 threads, 8x8 micro-tile per thread.
// Requires M%128==0, N%128==0, K%16==0 (true for all uses here).
// ---------------------------------------------------------------------------
#define BM 128
#define BN 128
#define BK 16

template<int RELU>
__global__ void gemm_kernel(const float* __restrict__ A,
                            const float* __restrict__ B,
                            const float* __restrict__ bias,
                            float* __restrict__ C,
                            int M, int N, int K) {
    __shared__ float As[BK][BM];
    __shared__ float Bs[BK][BN];

    int tid = threadIdx.x;
    int bm  = blockIdx.y * BM;
    int bn  = blockIdx.x * BN;
    int tx  = tid & 15;   // 0..15 -> col group
    int ty  = tid >> 4;   // 0..15 -> row group

    float acc[8][8];
#pragma unroll
    for (int i = 0; i < 8; i++)
#pragma unroll
        for (int j = 0; j < 8; j++) acc[i][j] = 0.0f;

    for (int k0 = 0; k0 < K; k0 += BK) {
#pragma unroll
        for (int p = 0; p < 2; p++) {
            int idx = p * 256 + tid;
            // A tile: 128 rows x 16 cols, as float4 along K
            int m  = idx >> 2;
            int kk = (idx & 3) * 4;
            float4 av = *(const float4*)(A + (size_t)(bm + m) * K + k0 + kk);
            As[kk + 0][m] = av.x;
            As[kk + 1][m] = av.y;
            As[kk + 2][m] = av.z;
            As[kk + 3][m] = av.w;
            // B tile: 16 rows x 128 cols, as float4 along N
            int kb = idx >> 5;
            int n4 = (idx & 31) * 4;
            *(float4*)(&Bs[kb][n4]) =
                *(const float4*)(B + (size_t)(k0 + kb) * N + bn + n4);
        }
        __syncthreads();

#pragma unroll
        for (int k = 0; k < BK; k++) {
            float ra[8], rb[8];
#pragma unroll
            for (int i = 0; i < 8; i++) ra[i] = As[k][ty * 8 + i];
#pragma unroll
            for (int j = 0; j < 8; j++) rb[j] = Bs[k][tx * 8 + j];
#pragma unroll
            for (int i = 0; i < 8; i++)
#pragma unroll
                for (int j = 0; j < 8; j++) acc[i][j] += ra[i] * rb[j];
        }
        __syncthreads();
    }

    // Epilogue: bias (+ReLU), vectorized stores
#pragma unroll
    for (int i = 0; i < 8; i++) {
        int m = bm + ty * 8 + i;
        float* crow = C + (size_t)m * N + bn + tx * 8;
#pragma unroll
        for (int jv = 0; jv < 2; jv++) {
            float4 o;
            int n0 = bn + tx * 8 + jv * 4;
            o.x = acc[i][jv * 4 + 0] + bias[n0 + 0];
            o.y = acc[i][jv * 4 + 1] + bias[n0 + 1];
            o.z = acc[i][jv * 4 + 2] + bias[n0 + 2];
            o.w = acc[i][jv * 4 + 3] + bias[n0 + 3];
            if (RELU) {
                o.x = fmaxf(o.x, 0.0f); o.y = fmaxf(o.y, 0.0f);
                o.z = fmaxf(o.z, 0.0f); o.w = fmaxf(o.w, 0.0f);
            }
            *(float4*)(crow + jv * 4) = o;
        }
    }
}

// ---------------------------------------------------------------------------
// qe[row, h, e] = sum_d q[row, h*64+d] * edge_emb[e, d]
// One block per row. edge_emb (50x64) cached in smem.
// ---------------------------------------------------------------------------
__global__ void qe_kernel(const float* __restrict__ q,
                          const float* __restrict__ ee,
                          float* __restrict__ qe) {
    int row = blockIdx.x;
    int tid = threadIdx.x;
    __shared__ float qsh[Dd];
    __shared__ float eesh[Ee * HDd];
    for (int i = tid; i < Dd; i += 256)        qsh[i]  = q[(size_t)row * Dd + i];
    for (int i = tid; i < Ee * HDd; i += 256)  eesh[i] = ee[i];
    __syncthreads();
    for (int o = tid; o < Hh * Ee; o += 256) {
        int hh = o / Ee, e = o % Ee;
        float s = 0.0f;
#pragma unroll
        for (int d = 0; d < HDd; d++) s += qsh[hh * HDd + d] * eesh[e * HDd + d];
        qe[(size_t)row * (Hh * Ee) + o] = s;
    }
}

// ---------------------------------------------------------------------------
// Fused attention: one block per (b, h). K/V staged in dynamic smem.
// scores = (q.k + qe[et]) * scale  (masked -> -1e9), softmax over j, out = att@V
// NOTE: adj is int32 (bool inputs are normalized to int32 by the harness).
// ---------------------------------------------------------------------------
#define ATTN_SMEM_FLOATS (2 * 256 * 65 + 64 + 64 + 256 + 256 + 8 + 8)

__device__ __forceinline__ float warp_max_f(float v) {
#pragma unroll
    for (int o = 16; o > 0; o >>= 1) v = fmaxf(v, __shfl_xor_sync(0xffffffffu, v, o));
    return v;
}
__device__ __forceinline__ float warp_sum_f(float v) {
#pragma unroll
    for (int o = 16; o > 0; o >>= 1) v += __shfl_xor_sync(0xffffffffu, v, o);
    return v;
}

__global__ void attn_kernel(const float* __restrict__ q,
                            const float* __restrict__ k,
                            const float* __restrict__ v,
                            const float* __restrict__ qe,
                            const int* __restrict__ et,
                            const int* __restrict__ adj,
                            float* __restrict__ out) {
    int bh = blockIdx.x;
    int b  = bh / Hh;
    int h  = bh % Hh;
    int tid  = threadIdx.x;
    int lane = tid & 31;
    int wid  = tid >> 5;

    extern __shared__ float sm[];
    float* Ksh   = sm;                   // 256*65
    float* Vsh   = Ksh + 256 * 65;       // 256*65
    float* qsh   = Vsh + 256 * 65;       // 64
    float* qesh  = qsh + 64;             // 64 (50 used)
    float* attsh = qesh + 64;            // 256
    float* red   = attsh + 256;          // 256
    float* smax  = red + 256;            // 8
    float* ssum  = smax + 8;             // 8

    // Stage K, V for this (b, h)
    for (int idx = tid; idx < Ll * HDd; idx += 256) {
        int j = idx >> 6, d = idx & 63;
        size_t g = (size_t)(b * Ll + j) * Dd + h * HDd + d;
        Ksh[j * 65 + d] = k[g];
        Vsh[j * 65 + d] = v[g];
    }
    __syncthreads();

    const float scale = 0.125f;  // 1/sqrt(64)

    for (int i = 0; i < Ll; i++) {
        size_t row = (size_t)b * Ll + i;
        if (tid < 64)       qsh[tid]       = q[row * Dd + h * HDd + tid];
        else if (tid < 114) qesh[tid - 64] = qe[(row * Hh + h) * Ee + (tid - 64)];
        __syncthreads();

        int j = tid;
        float s = 0.0f;
#pragma unroll
        for (int d = 0; d < HDd; d++) s += qsh[d] * Ksh[j * 65 + d];
        s += qesh[et[row * Ll + j]];
        float val = adj[row * Ll + j] ? s * scale : -1e9f;

        // block max
        float m = warp_max_f(val);
        if (lane == 0) smax[wid] = m;
        __syncthreads();
        float mx = warp_max_f((lane < 8) ? smax[lane] : -1e30f);

        float p = expf(val - mx);

        // block sum
        float su = warp_sum_f(p);
        if (lane == 0) ssum[wid] = su;
        __syncthreads();
        float tot = warp_sum_f((lane < 8) ? ssum[lane] : 0.0f);

        float att = p / tot;
        attsh[tid] = att;
        __syncthreads();

        // AV: d = tid%64, j-chunk = tid/64
        int d  = tid & 63;
        int jc = tid >> 6;
        float acc = 0.0f;
#pragma unroll
        for (int jj = jc * 64; jj < jc * 64 + 64; jj++)
            acc += attsh[jj] * Vsh[jj * 65 + d];
        red[tid] = acc;
        __syncthreads();
        if (tid < 64)
            out[row * Dd + h * HDd + tid] =
                red[tid] + red[64 + tid] + red[128 + tid] + red[192 + tid];
        __syncthreads();
    }
}

// ---------------------------------------------------------------------------
// Fused residual + LayerNorm: h = LN(h + delta) * g + beta   (in-place on h)
// One block per row (768 = 3 * 256).
// ---------------------------------------------------------------------------
__global__ void ln_kernel(float* __restrict__ h,
                          const float* __restrict__ delta,
                          const float* __restrict__ g,
                          const float* __restrict__ beta) {
    int row = blockIdx.x;
    int tid = threadIdx.x;
    __shared__ float s1[8], s2[8], mv[2];
    size_t base = (size_t)row * Dd;

    float x0 = h[base + tid]       + delta[base + tid];
    float x1 = h[base + tid + 256] + delta[base + tid + 256];
    float x2 = h[base + tid + 512] + delta[base + tid + 512];

    float s  = x0 + x1 + x2;
    float ss = x0 * x0 + x1 * x1 + x2 * x2;
#pragma unroll
    for (int o = 16; o > 0; o >>= 1) {
        s  += __shfl_xor_sync(0xffffffffu, s, o);
        ss += __shfl_xor_sync(0xffffffffu, ss, o);
    }
    int lane = tid & 31, wid = tid >> 5;
    if (lane == 0) { s1[wid] = s; s2[wid] = ss; }
    __syncthreads();
    if (tid == 0) {
        float S = 0.0f, SS = 0.0f;
#pragma unroll
        for (int i = 0; i < 8; i++) { S += s1[i]; SS += s2[i]; }
        float mean = S / (float)Dd;
        mv[0] = mean;
        mv[1] = rsqrtf(SS / (float)Dd - mean * mean + 1e-5f);
    }
    __syncthreads();
    float mean = mv[0], inv = mv[1];
    h[base + tid]       = (x0 - mean) * inv * g[tid]       + beta[tid];
    h[base + tid + 256] = (x1 - mean) * inv * g[tid + 256] + beta[tid + 256];
    h[base + tid + 512] = (x2 - mean) * inv * g[tid + 512] + beta[tid + 512];
}

// ---------------------------------------------------------------------------
// CLS head: out[b, c] = h[b, 0, :] . cls_W[:, c] + cls_b[c]   (16x2 outputs)
// ---------------------------------------------------------------------------
__global__ void cls_kernel(const float* __restrict__ h,
                           const float* __restrict__ W,
                           const float* __restrict__ bias,
                           float* __restrict__ out) {
    int w    = threadIdx.x >> 5;
    int lane = threadIdx.x & 31;
    for (int o = w * 4; o < w * 4 + 4; o++) {   // 8 warps x 4 = 32 outputs
        int b = o >> 1, c = o & 1;
        float s = 0.0f;
        for (int d = lane; d < Dd; d += 32)
            s += h[(size_t)(b * Ll) * Dd + d] * W[(size_t)d * Cc + c];
#pragma unroll
        for (int off = 16; off > 0; off >>= 1) s += __shfl_xor_sync(0xffffffffu, s, off);
        if (lane == 0) out[o] = s + bias[c];
    }
}

// ---------------------------------------------------------------------------
// Launch
// ---------------------------------------------------------------------------
extern "C" void kernel_launch(void* const* d_in, const int* in_sizes, int n_in,
                              void* d_out, int out_size) {
    const int*   word_ids = (const int*)d_in[0];
    const int*   adj      = (const int*)d_in[1];   // bool -> int32 (harness)
    const int*   et       = (const int*)d_in[2];
    const float* wemb     = (const float*)d_in[3];
    const float* eemb     = (const float*)d_in[4];
    const float* Wq   = (const float*)d_in[5];
    const float* bq   = (const float*)d_in[6];
    const float* Wk   = (const float*)d_in[7];
    const float* bk   = (const float*)d_in[8];
    const float* Wv   = (const float*)d_in[9];
    const float* bv   = (const float*)d_in[10];
    const float* Wo   = (const float*)d_in[11];
    const float* bo   = (const float*)d_in[12];
    const float* ln1g = (const float*)d_in[13];
    const float* ln1b = (const float*)d_in[14];
    const float* W1   = (const float*)d_in[15];
    const float* b1   = (const float*)d_in[16];
    const float* W2   = (const float*)d_in[17];
    const float* b2   = (const float*)d_in[18];
    const float* ln2g = (const float*)d_in[19];
    const float* ln2b = (const float*)d_in[20];
    const float* clsW = (const float*)d_in[21];
    const float* clsb = (const float*)d_in[22];

    float *h, *q, *k, *v, *ao, *t, *ff, *qe;
    cudaGetSymbolAddress((void**)&h,  g_h);
    cudaGetSymbolAddress((void**)&q,  g_q);
    cudaGetSymbolAddress((void**)&k,  g_k);
    cudaGetSymbolAddress((void**)&v,  g_v);
    cudaGetSymbolAddress((void**)&ao, g_ao);
    cudaGetSymbolAddress((void**)&t,  g_t);
    cudaGetSymbolAddress((void**)&ff, g_ff);
    cudaGetSymbolAddress((void**)&qe, g_qe);

    int attn_smem = ATTN_SMEM_FLOATS * sizeof(float);
    cudaFuncSetAttribute(attn_kernel,
                         cudaFuncAttributeMaxDynamicSharedMemorySize, attn_smem);

    embed_kernel<<<ROWS * Dd / 256, 256>>>(word_ids, wemb, h);

    dim3 gD(Dd / BN, ROWS / BM);   // (6, 32)
    dim3 gF(Ff / BN, ROWS / BM);   // (24, 32)

    for (int l = 0; l < NLl; l++) {
        gemm_kernel<0><<<gD, 256>>>(h, Wq + (size_t)l * Dd * Dd, bq + l * Dd, q, ROWS, Dd, Dd);
        gemm_kernel<0><<<gD, 256>>>(h, Wk + (size_t)l * Dd * Dd, bk + l * Dd, k, ROWS, Dd, Dd);
        gemm_kernel<0><<<gD, 256>>>(h, Wv + (size_t)l * Dd * Dd, bv + l * Dd, v, ROWS, Dd, Dd);

        qe_kernel<<<ROWS, 256>>>(q, eemb, qe);
        attn_kernel<<<Bb * Hh, 256, attn_smem>>>(q, k, v, qe, et, adj, ao);

        gemm_kernel<0><<<gD, 256>>>(ao, Wo + (size_t)l * Dd * Dd, bo + l * Dd, t, ROWS, Dd, Dd);
        ln_kernel<<<ROWS, 256>>>(h, t, ln1g + l * Dd, ln1b + l * Dd);

        gemm_kernel<1><<<gF, 256>>>(h, W1 + (size_t)l * Dd * Ff, b1 + l * Ff, ff, ROWS, Ff, Dd);
        gemm_kernel<0><<<gD, 256>>>(ff, W2 + (size_t)l * Ff * Dd, b2 + l * Dd, t, ROWS, Dd, Ff);
        ln_kernel<<<ROWS, 256>>>(h, t, ln2g + l * Dd, ln2b + l * Dd);
    }

    cls_kernel<<<1, 256>>>(h, clsW, clsb, (float*)d_out);
}

// round 4
// speedup vs baseline: 1.0017x; 1.0017x over previous
#include <cuda_runtime.h>
#include <cuda_bf16.h>
#include <math.h>

// Problem dims
#define Bb   16
#define Ll   256
#define Dd   768
#define Hh   12
#define HDd  64
#define NLl  4
#define Ff   3072
#define Ee   50
#define Cc   2
#define ROWS (Bb * Ll)   // 4096

// ---------------------------------------------------------------------------
// Scratch (device globals; no allocations allowed)
// ---------------------------------------------------------------------------
__device__ float g_h [ROWS * Dd];
__device__ float g_q [ROWS * Dd];
__device__ float g_k [ROWS * Dd];
__device__ float g_v [ROWS * Dd];
__device__ float g_ao[ROWS * Dd];
__device__ float g_t [ROWS * Dd];
__device__ float g_ff[ROWS * Ff];
__device__ float g_qe[ROWS * Hh * Ee];

// ---------------------------------------------------------------------------
// Embedding: h[b,l,d] = word_emb[ids[b,l], d] + pos_emb(l, d)
// ---------------------------------------------------------------------------
__global__ void embed_kernel(const int* __restrict__ ids,
                             const float* __restrict__ wemb,
                             float* __restrict__ h) {
    int idx = blockIdx.x * blockDim.x + threadIdx.x;   // < ROWS*Dd
    int d   = idx % Dd;
    int row = idx / Dd;
    int l   = row % Ll;
    int j   = d >> 1;
    float ang = (float)l * expf(-9.210340371976184f * (float)(2 * j) / (float)Dd);
    float pe  = (d & 1) ? cosf(ang) : sinf(ang);
    h[idx] = wemb[(size_t)ids[row] * Dd + d] + pe;
}

// ---------------------------------------------------------------------------
// Generic fp32 GEMM: C[M,N] = A[M,K] @ B[K,N] + bias[N]  (optional ReLU)
// BM=BN=128, BK=16, 256 threads, 8x8 micro-tile per thread.
// Requires M%128==0, N%128==0, K%16==0 (true for all uses here).
// ---------------------------------------------------------------------------
#define BM 128
#define BN 128
#define BK 16

template<int RELU>
__global__ void gemm_kernel(const float* __restrict__ A,
                            const float* __restrict__ B,
                            const float* __restrict__ bias,
                            float* __restrict__ C,
                            int M, int N, int K) {
    __shared__ float As[BK][BM];
    __shared__ float Bs[BK][BN];

    int tid = threadIdx.x;
    int bm  = blockIdx.y * BM;
    int bn  = blockIdx.x * BN;
    int tx  = tid & 15;   // 0..15 -> col group
    int ty  = tid >> 4;   // 0..15 -> row group

    float acc[8][8];
#pragma unroll
    for (int i = 0; i < 8; i++)
#pragma unroll
        for (int j = 0; j < 8; j++) acc[i][j] = 0.0f;

    for (int k0 = 0; k0 < K; k0 += BK) {
#pragma unroll
        for (int p = 0; p < 2; p++) {
            int idx = p * 256 + tid;
            // A tile: 128 rows x 16 cols, as float4 along K
            int m  = idx >> 2;
            int kk = (idx & 3) * 4;
            float4 av = *(const float4*)(A + (size_t)(bm + m) * K + k0 + kk);
            As[kk + 0][m] = av.x;
            As[kk + 1][m] = av.y;
            As[kk + 2][m] = av.z;
            As[kk + 3][m] = av.w;
            // B tile: 16 rows x 128 cols, as float4 along N
            int kb = idx >> 5;
            int n4 = (idx & 31) * 4;
            *(float4*)(&Bs[kb][n4]) =
                *(const float4*)(B + (size_t)(k0 + kb) * N + bn + n4);
        }
        __syncthreads();

#pragma unroll
        for (int k = 0; k < BK; k++) {
            float ra[8], rb[8];
#pragma unroll
            for (int i = 0; i < 8; i++) ra[i] = As[k][ty * 8 + i];
#pragma unroll
            for (int j = 0; j < 8; j++) rb[j] = Bs[k][tx * 8 + j];
#pragma unroll
            for (int i = 0; i < 8; i++)
#pragma unroll
                for (int j = 0; j < 8; j++) acc[i][j] += ra[i] * rb[j];
        }
        __syncthreads();
    }

    // Epilogue: bias (+ReLU), vectorized stores
#pragma unroll
    for (int i = 0; i < 8; i++) {
        int m = bm + ty * 8 + i;
        float* crow = C + (size_t)m * N + bn + tx * 8;
#pragma unroll
        for (int jv = 0; jv < 2; jv++) {
            float4 o;
            int n0 = bn + tx * 8 + jv * 4;
            o.x = acc[i][jv * 4 + 0] + bias[n0 + 0];
            o.y = acc[i][jv * 4 + 1] + bias[n0 + 1];
            o.z = acc[i][jv * 4 + 2] + bias[n0 + 2];
            o.w = acc[i][jv * 4 + 3] + bias[n0 + 3];
            if (RELU) {
                o.x = fmaxf(o.x, 0.0f); o.y = fmaxf(o.y, 0.0f);
                o.z = fmaxf(o.z, 0.0f); o.w = fmaxf(o.w, 0.0f);
            }
            *(float4*)(crow + jv * 4) = o;
        }
    }
}

// ---------------------------------------------------------------------------
// qe[row, h, e] = sum_d q[row, h*64+d] * edge_emb[e, d]
// One block per row. edge_emb (50x64) cached in smem.
// ---------------------------------------------------------------------------
__global__ void qe_kernel(const float* __restrict__ q,
                          const float* __restrict__ ee,
                          float* __restrict__ qe) {
    int row = blockIdx.x;
    int tid = threadIdx.x;
    __shared__ float qsh[Dd];
    __shared__ float eesh[Ee * HDd];
    for (int i = tid; i < Dd; i += 256)        qsh[i]  = q[(size_t)row * Dd + i];
    for (int i = tid; i < Ee * HDd; i += 256)  eesh[i] = ee[i];
    __syncthreads();
    for (int o = tid; o < Hh * Ee; o += 256) {
        int hh = o / Ee, e = o % Ee;
        float s = 0.0f;
#pragma unroll
        for (int d = 0; d < HDd; d++) s += qsh[hh * HDd + d] * eesh[e * HDd + d];
        qe[(size_t)row * (Hh * Ee) + o] = s;
    }
}

// ---------------------------------------------------------------------------
// Fused attention: one block per (b, h). K/V staged in dynamic smem.
// scores = (q.k + qe[et]) * scale  (masked -> -1e9), softmax over j, out = att@V
// NOTE: adj is int32 (bool inputs are normalized to int32 by the harness).
// ---------------------------------------------------------------------------
#define ATTN_SMEM_FLOATS (2 * 256 * 65 + 64 + 64 + 256 + 256 + 8 + 8)

__device__ __forceinline__ float warp_max_f(float v) {
#pragma unroll
    for (int o = 16; o > 0; o >>= 1) v = fmaxf(v, __shfl_xor_sync(0xffffffffu, v, o));
    return v;
}
__device__ __forceinline__ float warp_sum_f(float v) {
#pragma unroll
    for (int o = 16; o > 0; o >>= 1) v += __shfl_xor_sync(0xffffffffu, v, o);
    return v;
}

__global__ void attn_kernel(const float* __restrict__ q,
                            const float* __restrict__ k,
                            const float* __restrict__ v,
                            const float* __restrict__ qe,
                            const int* __restrict__ et,
                            const int* __restrict__ adj,
                            float* __restrict__ out) {
    int bh = blockIdx.x;
    int b  = bh / Hh;
    int h  = bh % Hh;
    int tid  = threadIdx.x;
    int lane = tid & 31;
    int wid  = tid >> 5;

    extern __shared__ float sm[];
    float* Ksh   = sm;                   // 256*65
    float* Vsh   = Ksh + 256 * 65;       // 256*65
    float* qsh   = Vsh + 256 * 65;       // 64
    float* qesh  = qsh + 64;             // 64 (50 used)
    float* attsh = qesh + 64;            // 256
    float* red   = attsh + 256;          // 256
    float* smax  = red + 256;            // 8
    float* ssum  = smax + 8;             // 8

    // Stage K, V for this (b, h)
    for (int idx = tid; idx < Ll * HDd; idx += 256) {
        int j = idx >> 6, d = idx & 63;
        size_t g = (size_t)(b * Ll + j) * Dd + h * HDd + d;
        Ksh[j * 65 + d] = k[g];
        Vsh[j * 65 + d] = v[g];
    }
    __syncthreads();

    const float scale = 0.125f;  // 1/sqrt(64)

    for (int i = 0; i < Ll; i++) {
        size_t row = (size_t)b * Ll + i;
        if (tid < 64)       qsh[tid]       = q[row * Dd + h * HDd + tid];
        else if (tid < 114) qesh[tid - 64] = qe[(row * Hh + h) * Ee + (tid - 64)];
        __syncthreads();

        int j = tid;
        float s = 0.0f;
#pragma unroll
        for (int d = 0; d < HDd; d++) s += qsh[d] * Ksh[j * 65 + d];
        s += qesh[et[row * Ll + j]];
        float val = adj[row * Ll + j] ? s * scale : -1e9f;

        // block max
        float m = warp_max_f(val);
        if (lane == 0) smax[wid] = m;
        __syncthreads();
        float mx = warp_max_f((lane < 8) ? smax[lane] : -1e30f);

        float p = expf(val - mx);

        // block sum
        float su = warp_sum_f(p);
        if (lane == 0) ssum[wid] = su;
        __syncthreads();
        float tot = warp_sum_f((lane < 8) ? ssum[lane] : 0.0f);

        float att = p / tot;
        attsh[tid] = att;
        __syncthreads();

        // AV: d = tid%64, j-chunk = tid/64
        int d  = tid & 63;
        int jc = tid >> 6;
        float acc = 0.0f;
#pragma unroll
        for (int jj = jc * 64; jj < jc * 64 + 64; jj++)
            acc += attsh[jj] * Vsh[jj * 65 + d];
        red[tid] = acc;
        __syncthreads();
        if (tid < 64)
            out[row * Dd + h * HDd + tid] =
                red[tid] + red[64 + tid] + red[128 + tid] + red[192 + tid];
        __syncthreads();
    }
}

// ---------------------------------------------------------------------------
// Fused residual + LayerNorm: h = LN(h + delta) * g + beta   (in-place on h)
// One block per row (768 = 3 * 256).
// ---------------------------------------------------------------------------
__global__ void ln_kernel(float* __restrict__ h,
                          const float* __restrict__ delta,
                          const float* __restrict__ g,
                          const float* __restrict__ beta) {
    int row = blockIdx.x;
    int tid = threadIdx.x;
    __shared__ float s1[8], s2[8], mv[2];
    size_t base = (size_t)row * Dd;

    float x0 = h[base + tid]       + delta[base + tid];
    float x1 = h[base + tid + 256] + delta[base + tid + 256];
    float x2 = h[base + tid + 512] + delta[base + tid + 512];

    float s  = x0 + x1 + x2;
    float ss = x0 * x0 + x1 * x1 + x2 * x2;
#pragma unroll
    for (int o = 16; o > 0; o >>= 1) {
        s  += __shfl_xor_sync(0xffffffffu, s, o);
        ss += __shfl_xor_sync(0xffffffffu, ss, o);
    }
    int lane = tid & 31, wid = tid >> 5;
    if (lane == 0) { s1[wid] = s; s2[wid] = ss; }
    __syncthreads();
    if (tid == 0) {
        float S = 0.0f, SS = 0.0f;
#pragma unroll
        for (int i = 0; i < 8; i++) { S += s1[i]; SS += s2[i]; }
        float mean = S / (float)Dd;
        mv[0] = mean;
        mv[1] = rsqrtf(SS / (float)Dd - mean * mean + 1e-5f);
    }
    __syncthreads();
    float mean = mv[0], inv = mv[1];
    h[base + tid]       = (x0 - mean) * inv * g[tid]       + beta[tid];
    h[base + tid + 256] = (x1 - mean) * inv * g[tid + 256] + beta[tid + 256];
    h[base + tid + 512] = (x2 - mean) * inv * g[tid + 512] + beta[tid + 512];
}

// ---------------------------------------------------------------------------
// CLS head: out[b, c] = h[b, 0, :] . cls_W[:, c] + cls_b[c]   (16x2 outputs)
// ---------------------------------------------------------------------------
__global__ void cls_kernel(const float* __restrict__ h,
                           const float* __restrict__ W,
                           const float* __restrict__ bias,
                           float* __restrict__ out) {
    int w    = threadIdx.x >> 5;
    int lane = threadIdx.x & 31;
    for (int o = w * 4; o < w * 4 + 4; o++) {   // 8 warps x 4 = 32 outputs
        int b = o >> 1, c = o & 1;
        float s = 0.0f;
        for (int d = lane; d < Dd; d += 32)
            s += h[(size_t)(b * Ll) * Dd + d] * W[(size_t)d * Cc + c];
#pragma unroll
        for (int off = 16; off > 0; off >>= 1) s += __shfl_xor_sync(0xffffffffu, s, off);
        if (lane == 0) out[o] = s + bias[c];
    }
}

// ---------------------------------------------------------------------------
// Launch
// ---------------------------------------------------------------------------
extern "C" void kernel_launch(void* const* d_in, const int* in_sizes, int n_in,
                              void* d_out, int out_size) {
    const int*   word_ids = (const int*)d_in[0];
    const int*   adj      = (const int*)d_in[1];   // bool -> int32 (harness)
    const int*   et       = (const int*)d_in[2];
    const float* wemb     = (const float*)d_in[3];
    const float* eemb     = (const float*)d_in[4];
    const float* Wq   = (const float*)d_in[5];
    const float* bq   = (const float*)d_in[6];
    const float* Wk   = (const float*)d_in[7];
    const float* bk   = (const float*)d_in[8];
    const float* Wv   = (const float*)d_in[9];
    const float* bv   = (const float*)d_in[10];
    const float* Wo   = (const float*)d_in[11];
    const float* bo   = (const float*)d_in[12];
    const float* ln1g = (const float*)d_in[13];
    const float* ln1b = (const float*)d_in[14];
    const float* W1   = (const float*)d_in[15];
    const float* b1   = (const float*)d_in[16];
    const float* W2   = (const float*)d_in[17];
    const float* b2   = (const float*)d_in[18];
    const float* ln2g = (const float*)d_in[19];
    const float* ln2b = (const float*)d_in[20];
    const float* clsW = (const float*)d_in[21];
    const float* clsb = (const float*)d_in[22];

    float *h, *q, *k, *v, *ao, *t, *ff, *qe;
    cudaGetSymbolAddress((void**)&h,  g_h);
    cudaGetSymbolAddress((void**)&q,  g_q);
    cudaGetSymbolAddress((void**)&k,  g_k);
    cudaGetSymbolAddress((void**)&v,  g_v);
    cudaGetSymbolAddress((void**)&ao, g_ao);
    cudaGetSymbolAddress((void**)&t,  g_t);
    cudaGetSymbolAddress((void**)&ff, g_ff);
    cudaGetSymbolAddress((void**)&qe, g_qe);

    int attn_smem = ATTN_SMEM_FLOATS * sizeof(float);
    cudaFuncSetAttribute(attn_kernel,
                         cudaFuncAttributeMaxDynamicSharedMemorySize, attn_smem);

    embed_kernel<<<ROWS * Dd / 256, 256>>>(word_ids, wemb, h);

    dim3 gD(Dd / BN, ROWS / BM);   // (6, 32)
    dim3 gF(Ff / BN, ROWS / BM);   // (24, 32)

    for (int l = 0; l < NLl; l++) {
        gemm_kernel<0><<<gD, 256>>>(h, Wq + (size_t)l * Dd * Dd, bq + l * Dd, q, ROWS, Dd, Dd);
        gemm_kernel<0><<<gD, 256>>>(h, Wk + (size_t)l * Dd * Dd, bk + l * Dd, k, ROWS, Dd, Dd);
        gemm_kernel<0><<<gD, 256>>>(h, Wv + (size_t)l * Dd * Dd, bv + l * Dd, v, ROWS, Dd, Dd);

        qe_kernel<<<ROWS, 256>>>(q, eemb, qe);
        attn_kernel<<<Bb * Hh, 256, attn_smem>>>(q, k, v, qe, et, adj, ao);

        gemm_kernel<0><<<gD, 256>>>(ao, Wo + (size_t)l * Dd * Dd, bo + l * Dd, t, ROWS, Dd, Dd);
        ln_kernel<<<ROWS, 256>>>(h, t, ln1g + l * Dd, ln1b + l * Dd);

        gemm_kernel<1><<<gF, 256>>>(h, W1 + (size_t)l * Dd * Ff, b1 + l * Ff, ff, ROWS, Ff, Dd);
        gemm_kernel<0><<<gD, 256>>>(ff, W2 + (size_t)l * Ff * Dd, b2 + l * Dd, t, ROWS, Dd, Ff);
        ln_kernel<<<ROWS, 256>>>(h, t, ln2g + l * Dd, ln2b + l * Dd);
    }

    cls_kernel<<<1, 256>>>(h, clsW, clsb, (float*)d_out);
}

// round 8
// speedup vs baseline: 2.1695x; 2.1658x over previous
#include <cuda_runtime.h>
#include <cuda_bf16.h>
#include <math.h>
#include <stdint.h>

#define Bb   16
#define Ll   256
#define Dd   768
#define Hh   12
#define HDd  64
#define NLl  4
#define Ff   3072
#define Ee   50
#define Cc   2
#define ROWS (Bb * Ll)

__device__ float g_h [ROWS * Dd];
__device__ float g_q [ROWS * Dd];
__device__ float g_k [ROWS * Dd];
__device__ float g_v [ROWS * Dd];
__device__ float g_ao[ROWS * Dd];
__device__ float g_t [ROWS * Dd];
__device__ float g_ff[ROWS * Ff];
__device__ float g_qe[ROWS * Hh * Ee];

// ---------------------------------------------------------------------------
__global__ void embed_kernel(const int* __restrict__ ids,
                             const float* __restrict__ wemb,
                             float* __restrict__ h) {
    int idx = blockIdx.x * blockDim.x + threadIdx.x;
    int d   = idx % Dd;
    int row = idx / Dd;
    int l   = row % Ll;
    int j   = d >> 1;
    float ang = (float)l * expf(-9.210340371976184f * (float)(2 * j) / (float)Dd);
    float pe  = (d & 1) ? cosf(ang) : sinf(ang);
    h[idx] = wemb[(size_t)ids[row] * Dd + d] + pe;
}

// ---------------------------------------------------------------------------
// Tensor-core GEMM via bf16 split-3: C = A@B + bias (optional ReLU)
// BM=BN=128, BK=32, 256 threads, 8 warps (2x4), warp tile 64x32 (4x4 m16n8k16)
// ---------------------------------------------------------------------------
#define ASTR 20   // uint32 smem row stride (16 k-pairs + 4 pad)

__device__ __forceinline__ void split_pair(float a0, float a1,
                                           uint32_t& hi, uint32_t& lo) {
    __nv_bfloat16 h0 = __float2bfloat16(a0);
    __nv_bfloat16 h1 = __float2bfloat16(a1);
    __nv_bfloat16 l0 = __float2bfloat16(a0 - __bfloat162float(h0));
    __nv_bfloat16 l1 = __float2bfloat16(a1 - __bfloat162float(h1));
    __nv_bfloat162 H = __halves2bfloat162(h0, h1);
    __nv_bfloat162 L = __halves2bfloat162(l0, l1);
    hi = *reinterpret_cast<uint32_t*>(&H);
    lo = *reinterpret_cast<uint32_t*>(&L);
}

__device__ __forceinline__ void mma_bf16(float* c, const uint32_t* a,
                                         const uint32_t* b) {
    asm volatile(
        "mma.sync.aligned.m16n8k16.row.col.f32.bf16.bf16.f32 "
        "{%0,%1,%2,%3}, {%4,%5,%6,%7}, {%8,%9}, {%0,%1,%2,%3};\n"
        : "+f"(c[0]), "+f"(c[1]), "+f"(c[2]), "+f"(c[3])
        : "r"(a[0]), "r"(a[1]), "r"(a[2]), "r"(a[3]), "r"(b[0]), "r"(b[1]));
}

template<int RELU>
__device__ __forceinline__ void gemm_core(const float* __restrict__ A,
                                          const float* __restrict__ B,
                                          const float* __restrict__ bias,
                                          float* __restrict__ C,
                                          int N, int K, int bm, int bn) {
    __shared__ uint32_t Ah[128 * ASTR], Al[128 * ASTR];
    __shared__ uint32_t Bh[128 * ASTR], Bl[128 * ASTR];

    int tid  = threadIdx.x;
    int lane = tid & 31, wid = tid >> 5;
    int wm = wid >> 2, wn = wid & 3;
    int g  = lane >> 2, tig = lane & 3;

    float c[4][4][4];
#pragma unroll
    for (int mt = 0; mt < 4; mt++)
#pragma unroll
        for (int nt = 0; nt < 4; nt++)
#pragma unroll
            for (int r = 0; r < 4; r++) c[mt][nt][r] = 0.0f;

    float ra[16], rb0[8], rb1[8];

    auto ldgA = [&](int k0) {
#pragma unroll
        for (int cc = 0; cc < 4; cc++) {
            int idx = cc * 256 + tid;
            int m = idx >> 3, kc = idx & 7;
            float4 t4 = *(const float4*)(A + (size_t)(bm + m) * K + k0 + kc * 4);
            ra[cc * 4 + 0] = t4.x; ra[cc * 4 + 1] = t4.y;
            ra[cc * 4 + 2] = t4.z; ra[cc * 4 + 3] = t4.w;
        }
    };
    auto ldgB = [&](int k0) {
#pragma unroll
        for (int cc = 0; cc < 8; cc++) {
            int idx = cc * 256 + tid;
            int n = idx & 127, kp = idx >> 7;
            rb0[cc] = B[(size_t)(k0 + 2 * kp) * N + bn + n];
            rb1[cc] = B[(size_t)(k0 + 2 * kp + 1) * N + bn + n];
        }
    };

    int niter = K / 32;
    ldgA(0); ldgB(0);

    for (int it = 0; it < niter; it++) {
#pragma unroll
        for (int cc = 0; cc < 4; cc++) {
            int idx = cc * 256 + tid;
            int m = idx >> 3, kc = idx & 7;
            uint32_t h0, l0, h1, l1;
            split_pair(ra[cc * 4 + 0], ra[cc * 4 + 1], h0, l0);
            split_pair(ra[cc * 4 + 2], ra[cc * 4 + 3], h1, l1);
            Ah[m * ASTR + kc * 2]     = h0;  Al[m * ASTR + kc * 2]     = l0;
            Ah[m * ASTR + kc * 2 + 1] = h1;  Al[m * ASTR + kc * 2 + 1] = l1;
        }
#pragma unroll
        for (int cc = 0; cc < 8; cc++) {
            int idx = cc * 256 + tid;
            int n = idx & 127, kp = idx >> 7;
            uint32_t hh, ll;
            split_pair(rb0[cc], rb1[cc], hh, ll);
            Bh[n * ASTR + kp] = hh;  Bl[n * ASTR + kp] = ll;
        }
        __syncthreads();

        if (it + 1 < niter) { ldgA((it + 1) * 32); ldgB((it + 1) * 32); }

#pragma unroll
        for (int ks = 0; ks < 2; ks++) {
            uint32_t ah[4][4], al[4][4], bhf[4][2], blf[4][2];
            int kp0 = ks * 8 + tig;
#pragma unroll
            for (int mt = 0; mt < 4; mt++) {
                int r0 = (wm * 64 + mt * 16 + g) * ASTR;
                int r1 = r0 + 8 * ASTR;
                ah[mt][0] = Ah[r0 + kp0];     ah[mt][1] = Ah[r1 + kp0];
                ah[mt][2] = Ah[r0 + kp0 + 4]; ah[mt][3] = Ah[r1 + kp0 + 4];
                al[mt][0] = Al[r0 + kp0];     al[mt][1] = Al[r1 + kp0];
                al[mt][2] = Al[r0 + kp0 + 4]; al[mt][3] = Al[r1 + kp0 + 4];
            }
#pragma unroll
            for (int nt = 0; nt < 4; nt++) {
                int rn = (wn * 32 + nt * 8 + g) * ASTR;
                bhf[nt][0] = Bh[rn + kp0];  bhf[nt][1] = Bh[rn + kp0 + 4];
                blf[nt][0] = Bl[rn + kp0];  blf[nt][1] = Bl[rn + kp0 + 4];
            }
#pragma unroll
            for (int mt = 0; mt < 4; mt++)
#pragma unroll
                for (int nt = 0; nt < 4; nt++) {
                    mma_bf16(c[mt][nt], ah[mt], bhf[nt]);
                    mma_bf16(c[mt][nt], ah[mt], blf[nt]);
                    mma_bf16(c[mt][nt], al[mt], bhf[nt]);
                }
        }
        __syncthreads();
    }

#pragma unroll
    for (int mt = 0; mt < 4; mt++) {
        int row = bm + wm * 64 + mt * 16 + g;
#pragma unroll
        for (int nt = 0; nt < 4; nt++) {
            int col = bn + wn * 32 + nt * 8 + 2 * tig;
            float b0 = bias[col], b1 = bias[col + 1];
            float v0 = c[mt][nt][0] + b0, v1 = c[mt][nt][1] + b1;
            float v2 = c[mt][nt][2] + b0, v3 = c[mt][nt][3] + b1;
            if (RELU) {
                v0 = fmaxf(v0, 0.f); v1 = fmaxf(v1, 0.f);
                v2 = fmaxf(v2, 0.f); v3 = fmaxf(v3, 0.f);
            }
            float2 p0 = {v0, v1}, p1 = {v2, v3};
            *(float2*)&C[(size_t)row * N + col]       = p0;
            *(float2*)&C[(size_t)(row + 8) * N + col] = p1;
        }
    }
}

template<int RELU>
__global__ void __launch_bounds__(256) gemm_bf16x3(const float* __restrict__ A,
        const float* __restrict__ B, const float* __restrict__ bias,
        float* __restrict__ C, int N, int K) {
    gemm_core<RELU>(A, B, bias, C, N, K, blockIdx.y * 128, blockIdx.x * 128);
}

__global__ void __launch_bounds__(256) gemm_qkv(const float* __restrict__ A,
        const float* __restrict__ Wq, const float* __restrict__ Wk,
        const float* __restrict__ Wv, const float* __restrict__ bq,
        const float* __restrict__ bk, const float* __restrict__ bv,
        float* __restrict__ oq, float* __restrict__ ok, float* __restrict__ ov,
        int N, int K) {
    int z = blockIdx.z;
    const float* W  = (z == 0) ? Wq : (z == 1) ? Wk : Wv;
    const float* bb = (z == 0) ? bq : (z == 1) ? bk : bv;
    float*       O  = (z == 0) ? oq : (z == 1) ? ok : ov;
    gemm_core<0>(A, W, bb, O, N, K, blockIdx.y * 128, blockIdx.x * 128);
}

// ---------------------------------------------------------------------------
__global__ void qe_kernel(const float* __restrict__ q,
                          const float* __restrict__ ee,
                          float* __restrict__ qe) {
    int row = blockIdx.x;
    int tid = threadIdx.x;
    __shared__ float qsh[Dd];
    __shared__ float eesh[Ee * HDd];
    for (int i = tid; i < Dd; i += 256)        qsh[i]  = q[(size_t)row * Dd + i];
    for (int i = tid; i < Ee * HDd; i += 256)  eesh[i] = ee[i];
    __syncthreads();
    for (int o = tid; o < Hh * Ee; o += 256) {
        int hh = o / Ee, e = o % Ee;
        float s = 0.0f;
#pragma unroll
        for (int d = 0; d < HDd; d++) s += qsh[hh * HDd + d] * eesh[e * HDd + d];
        qe[(size_t)row * (Hh * Ee) + o] = s;
    }
}

// ---------------------------------------------------------------------------
// Warp-tiled fused attention: block per (b,h); 8 warps; 8 queries per warp.
// smem: Ksh 256x65 | Vsh 256x64 | attw 8x2048 | qew 8x416
// ---------------------------------------------------------------------------
#define ATTN_SMEM_BYTES ((256*65 + 256*64 + 8*2048 + 8*416) * 4)

__global__ void __launch_bounds__(256) attn_kernel(
        const float* __restrict__ q, const float* __restrict__ k,
        const float* __restrict__ v, const float* __restrict__ qe,
        const int* __restrict__ et, const int* __restrict__ adj,
        float* __restrict__ out) {
    int bh = blockIdx.x;
    int b = bh / Hh, h = bh % Hh;
    int tid = threadIdx.x, lane = tid & 31, wid = tid >> 5;

    extern __shared__ float sm[];
    float* Ksh  = sm;                                    // [j*65+d]
    float* Vsh  = Ksh + 256 * 65;                        // [j*64+d]
    float* attw = Vsh + 256 * 64 + wid * 2048;           // per-warp
    float* qew  = Vsh + 256 * 64 + 8 * 2048 + wid * 416; // per-warp

    for (int idx = tid; idx < 256 * 64; idx += 256) {
        int j = idx >> 6, d = idx & 63;
        size_t gg = (size_t)(b * Ll + j) * Dd + h * HDd + d;
        Ksh[j * 65 + d] = k[gg];
        Vsh[j * 64 + d] = v[gg];
    }
    __syncthreads();

    for (int pass = 0; pass < 4; pass++) {
        int qi0 = pass * 64 + wid * 8;

        // q tile in registers: lane holds qi=lane&7, d-block=lane>>3 (16 d's)
        float qreg[16];
        {
            const float* qp = q + (size_t)(b * Ll + qi0 + (lane & 7)) * Dd
                                + h * HDd + (lane >> 3) * 16;
#pragma unroll
            for (int r = 0; r < 16; r++) qreg[r] = qp[r];
        }
        for (int x = lane; x < 8 * Ee; x += 32) {
            int qi = x / Ee, e = x - qi * Ee;
            qew[qi * 52 + e] = qe[((size_t)(b * Ll + qi0 + qi) * Hh + h) * Ee + e];
        }
        __syncwarp();

        float s[8][8];
#pragma unroll
        for (int qi = 0; qi < 8; qi++)
#pragma unroll
            for (int t = 0; t < 8; t++) s[qi][t] = 0.0f;

        for (int dblk = 0; dblk < 4; dblk++) {
#pragma unroll
            for (int r = 0; r < 16; r++) {
                int d = dblk * 16 + r;
                float kv[8];
#pragma unroll
                for (int t = 0; t < 8; t++) kv[t] = Ksh[(t * 32 + lane) * 65 + d];
#pragma unroll
                for (int qi = 0; qi < 8; qi++) {
                    float qd = __shfl_sync(0xffffffffu, qreg[r], dblk * 8 + qi);
#pragma unroll
                    for (int t = 0; t < 8; t++) s[qi][t] = fmaf(qd, kv[t], s[qi][t]);
                }
            }
        }

        const int* etp = et  + (size_t)(b * Ll + qi0) * Ll;
        const int* adp = adj + (size_t)(b * Ll + qi0) * Ll;
#pragma unroll
        for (int qi = 0; qi < 8; qi++)
#pragma unroll
            for (int t = 0; t < 8; t++) {
                int j = t * 32 + lane;
                float eb = qew[qi * 52 + etp[qi * Ll + j]];
                s[qi][t] = adp[qi * Ll + j] ? (s[qi][t] + eb) * 0.125f : -1e9f;
            }

#pragma unroll
        for (int qi = 0; qi < 8; qi++) {
            float mx = s[qi][0];
#pragma unroll
            for (int t = 1; t < 8; t++) mx = fmaxf(mx, s[qi][t]);
#pragma unroll
            for (int o = 16; o > 0; o >>= 1)
                mx = fmaxf(mx, __shfl_xor_sync(0xffffffffu, mx, o));
            float sum = 0.0f;
#pragma unroll
            for (int t = 0; t < 8; t++) {
                float p = __expf(s[qi][t] - mx);
                s[qi][t] = p;
                sum += p;
            }
#pragma unroll
            for (int o = 16; o > 0; o >>= 1)
                sum += __shfl_xor_sync(0xffffffffu, sum, o);
            float inv = 1.0f / sum;
#pragma unroll
            for (int t = 0; t < 8; t++) {
                int j = t * 32 + lane;
                attw[j * 8 + ((qi + (j >> 2)) & 7)] = s[qi][t] * inv;
            }
        }
        __syncwarp();

        float o0[8], o1[8];
#pragma unroll
        for (int qi = 0; qi < 8; qi++) { o0[qi] = 0.0f; o1[qi] = 0.0f; }
        for (int j0 = 0; j0 < 256; j0 += 32) {
#pragma unroll
            for (int jj = 0; jj < 32; jj++) {
                int j = j0 + jj;
                float4 A0 = *(const float4*)&attw[j * 8];
                float4 A1 = *(const float4*)&attw[j * 8 + 4];
                float av[8] = {A0.x, A0.y, A0.z, A0.w, A1.x, A1.y, A1.z, A1.w};
                float v0 = Vsh[j * 64 + lane];
                float v1 = Vsh[j * 64 + lane + 32];
#pragma unroll
                for (int qi = 0; qi < 8; qi++) {
                    float a = av[(qi + ((jj >> 2) & 7)) & 7];
                    o0[qi] = fmaf(a, v0, o0[qi]);
                    o1[qi] = fmaf(a, v1, o1[qi]);
                }
            }
        }
#pragma unroll
        for (int qi = 0; qi < 8; qi++) {
            size_t rr = (size_t)(b * Ll + qi0 + qi) * Dd + h * HDd;
            out[rr + lane]      = o0[qi];
            out[rr + lane + 32] = o1[qi];
        }
        __syncwarp();
    }
}

// ---------------------------------------------------------------------------
__global__ void ln_kernel(float* __restrict__ h,
                          const float* __restrict__ delta,
                          const float* __restrict__ g,
                          const float* __restrict__ beta) {
    int row = blockIdx.x;
    int tid = threadIdx.x;
    __shared__ float s1[8], s2[8], mv[2];
    size_t base = (size_t)row * Dd;

    float x0 = h[base + tid]       + delta[base + tid];
    float x1 = h[base + tid + 256] + delta[base + tid + 256];
    float x2 = h[base + tid + 512] + delta[base + tid + 512];

    float s  = x0 + x1 + x2;
    float ss = x0 * x0 + x1 * x1 + x2 * x2;
#pragma unroll
    for (int o = 16; o > 0; o >>= 1) {
        s  += __shfl_xor_sync(0xffffffffu, s, o);
        ss += __shfl_xor_sync(0xffffffffu, ss, o);
    }
    int lane = tid & 31, wid = tid >> 5;
    if (lane == 0) { s1[wid] = s; s2[wid] = ss; }
    __syncthreads();
    if (tid == 0) {
        float S = 0.0f, SS = 0.0f;
#pragma unroll
        for (int i = 0; i < 8; i++) { S += s1[i]; SS += s2[i]; }
        float mean = S / (float)Dd;
        mv[0] = mean;
        mv[1] = rsqrtf(SS / (float)Dd - mean * mean + 1e-5f);
    }
    __syncthreads();
    float mean = mv[0], inv = mv[1];
    h[base + tid]       = (x0 - mean) * inv * g[tid]       + beta[tid];
    h[base + tid + 256] = (x1 - mean) * inv * g[tid + 256] + beta[tid + 256];
    h[base + tid + 512] = (x2 - mean) * inv * g[tid + 512] + beta[tid + 512];
}

// ---------------------------------------------------------------------------
__global__ void cls_kernel(const float* __restrict__ h,
                           const float* __restrict__ W,
                           const float* __restrict__ bias,
                           float* __restrict__ out) {
    int w    = threadIdx.x >> 5;
    int lane = threadIdx.x & 31;
    for (int o = w * 4; o < w * 4 + 4; o++) {
        int b = o >> 1, c = o & 1;
        float s = 0.0f;
        for (int d = lane; d < Dd; d += 32)
            s += h[(size_t)(b * Ll) * Dd + d] * W[(size_t)d * Cc + c];
#pragma unroll
        for (int off = 16; off > 0; off >>= 1) s += __shfl_xor_sync(0xffffffffu, s, off);
        if (lane == 0) out[o] = s + bias[c];
    }
}

// ---------------------------------------------------------------------------
extern "C" void kernel_launch(void* const* d_in, const int* in_sizes, int n_in,
                              void* d_out, int out_size) {
    const int*   word_ids = (const int*)d_in[0];
    const int*   adj      = (const int*)d_in[1];   // bool -> int32 (harness)
    const int*   et       = (const int*)d_in[2];
    const float* wemb     = (const float*)d_in[3];
    const float* eemb     = (const float*)d_in[4];
    const float* Wq   = (const float*)d_in[5];
    const float* bq   = (const float*)d_in[6];
    const float* Wk   = (const float*)d_in[7];
    const float* bk   = (const float*)d_in[8];
    const float* Wv   = (const float*)d_in[9];
    const float* bv   = (const float*)d_in[10];
    const float* Wo   = (const float*)d_in[11];
    const float* bo   = (const float*)d_in[12];
    const float* ln1g = (const float*)d_in[13];
    const float* ln1b = (const float*)d_in[14];
    const float* W1   = (const float*)d_in[15];
    const float* b1   = (const float*)d_in[16];
    const float* W2   = (const float*)d_in[17];
    const float* b2   = (const float*)d_in[18];
    const float* ln2g = (const float*)d_in[19];
    const float* ln2b = (const float*)d_in[20];
    const float* clsW = (const float*)d_in[21];
    const float* clsb = (const float*)d_in[22];

    float *h, *q, *k, *v, *ao, *t, *ff, *qe;
    cudaGetSymbolAddress((void**)&h,  g_h);
    cudaGetSymbolAddress((void**)&q,  g_q);
    cudaGetSymbolAddress((void**)&k,  g_k);
    cudaGetSymbolAddress((void**)&v,  g_v);
    cudaGetSymbolAddress((void**)&ao, g_ao);
    cudaGetSymbolAddress((void**)&t,  g_t);
    cudaGetSymbolAddress((void**)&ff, g_ff);
    cudaGetSymbolAddress((void**)&qe, g_qe);

    cudaFuncSetAttribute(attn_kernel,
                         cudaFuncAttributeMaxDynamicSharedMemorySize,
                         ATTN_SMEM_BYTES);

    embed_kernel<<<ROWS * Dd / 256, 256>>>(word_ids, wemb, h);

    dim3 gQKV(Dd / 128, ROWS / 128, 3);  // (6, 32, 3)
    dim3 gD(Dd / 128, ROWS / 128);       // (6, 32)
    dim3 gF(Ff / 128, ROWS / 128);       // (24, 32)

    for (int l = 0; l < NLl; l++) {
        gemm_qkv<<<gQKV, 256>>>(h,
            Wq + (size_t)l * Dd * Dd, Wk + (size_t)l * Dd * Dd,
            Wv + (size_t)l * Dd * Dd, bq + l * Dd, bk + l * Dd, bv + l * Dd,
            q, k, v, Dd, Dd);

        qe_kernel<<<ROWS, 256>>>(q, eemb, qe);
        attn_kernel<<<Bb * Hh, 256, ATTN_SMEM_BYTES>>>(q, k, v, qe, et, adj, ao);

        gemm_bf16x3<0><<<gD, 256>>>(ao, Wo + (size_t)l * Dd * Dd, bo + l * Dd,
                                    t, Dd, Dd);
        ln_kernel<<<ROWS, 256>>>(h, t, ln1g + l * Dd, ln1b + l * Dd);

        gemm_bf16x3<1><<<gF, 256>>>(h, W1 + (size_t)l * Dd * Ff, b1 + l * Ff,
                                    ff, Ff, Dd);
        gemm_bf16x3<0><<<gD, 256>>>(ff, W2 + (size_t)l * Ff * Dd, b2 + l * Dd,
                                    t, Dd, Ff);
        ln_kernel<<<ROWS, 256>>>(h, t, ln2g + l * Dd, ln2b + l * Dd);
    }

    cls_kernel<<<1, 256>>>(h, clsW, clsb, (float*)d_out);
}